// round 15
// baseline (speedup 1.0000x reference)
#include <cuda_runtime.h>
#include <cuda_bf16.h>
#include <cstdint>

// Problem constants
#define B_  16
#define S_  1024
#define T_  512
#define D_  512
#define H_  8
#define DH_ 64
#define DF_ 2048
#define E_  4
#define BSROWS (B_*S_)    // 16384
#define BTROWS (B_*T_)    // 8192
#define EPS_ 1e-5f

// ---------------- scratch (static __device__ — no allocation) ----------------
__device__ __nv_bfloat16  g_qkvbf[BSROWS*1536];   // self QKV bf16; reused: cross q + cross kv
__device__ __nv_bfloat16  g_attbf[BSROWS*D_];
__device__ float          g_pre  [BSROWS*D_];
__device__ float          g_xa   [BSROWS*D_];
__device__ __nv_bfloat16  g_xabf [BSROWS*D_];
__device__ float          g_xb   [BSROWS*D_];
__device__ __nv_bfloat16  g_xbbf [BSROWS*D_];
__device__ float          g_y    [BSROWS*D_];
__device__ __nv_bfloat16  g_hbf  [(size_t)BSROWS*E_*DF_];
__device__ __nv_bfloat16  g_xbf  [BSROWS*D_];
__device__ __nv_bfloat16  g_crbf [BTROWS*D_];
__device__ float          g_gates[BSROWS*E_];
__device__ float          g_gsum [E_];
// packed / transposed weights (bf16, [N][K] k-contiguous)
__device__ __nv_bfloat16  g_wqkvt [1536*D_];
__device__ float          g_bqkv  [1536];
__device__ __nv_bfloat16  g_wsaot [D_*D_];
__device__ __nv_bfloat16  g_wcaqt [D_*D_];
__device__ __nv_bfloat16  g_wcakvt[1024*D_];
__device__ float          g_bcakv [1024];
__device__ __nv_bfloat16  g_wcaot [D_*D_];
__device__ __nv_bfloat16  g_w1t   [(size_t)E_*DF_*D_];      // [8192][512]
__device__ __nv_bfloat16  g_w2t   [(size_t)D_*E_*DF_];      // [512][8192]

// ---------------- tiny utility kernels ----------------
__global__ void zero_gsum_kernel() {
    if (threadIdx.x < E_) g_gsum[threadIdx.x] = 0.f;
}

__global__ void aux_kernel(float* out, int out_size) {
    float s = 0.f;
#pragma unroll
    for (int e = 0; e < E_; e++) {
        float mn = g_gsum[e] * (1.f / (float)BSROWS);
        s += mn * mn;
    }
    if (out_size > BSROWS * D_) out[BSROWS * D_] = (float)E_ * s;
}

__global__ void pack3f_kernel(const float* __restrict__ a, const float* __restrict__ b,
                              const float* __restrict__ c, float* __restrict__ d)
{
    int i = blockIdx.x * blockDim.x + threadIdx.x;
    if (i < 512) {
        d[i] = a[i];
        if (b) d[512 + i]  = b[i];
        if (c) d[1024 + i] = c[i];
    }
}

__global__ void cvtbf_kernel(const float* __restrict__ s, __nv_bfloat16* __restrict__ d, int n4) {
    int i = blockIdx.x * blockDim.x + threadIdx.x;
    if (i < n4) {
        float4 f = ((const float4*)s)[i];
        __nv_bfloat162* dd = (__nv_bfloat162*)d + i * 2;
        dd[0] = __floats2bfloat162_rn(f.x, f.y);
        dd[1] = __floats2bfloat162_rn(f.z, f.w);
    }
}

// transpose-pack with z batching over a single contiguous src
__global__ void tpack3_kernel(const float* __restrict__ src, int srcCols, size_t srcZ,
                              __nv_bfloat16* __restrict__ dst, int dstLd,
                              int dRow0, int dCol0, int zRowStep, int zColStep)
{
    __shared__ float t[32][33];
    const int z = blockIdx.z;
    const int c0 = blockIdx.x * 32, r0 = blockIdx.y * 32;
    const float* s = src + (size_t)z * srcZ;
    const int row0 = dRow0 + z * zRowStep;
    const int col0 = dCol0 + z * zColStep;
#pragma unroll
    for (int i = 0; i < 4; i++) {
        int rr = threadIdx.y + i * 8;
        t[rr][threadIdx.x] = s[(size_t)(r0 + rr) * srcCols + c0 + threadIdx.x];
    }
    __syncthreads();
#pragma unroll
    for (int i = 0; i < 4; i++) {
        int rr = threadIdx.y + i * 8;
        dst[(size_t)(row0 + c0 + rr) * dstLd + col0 + r0 + threadIdx.x] =
            __float2bfloat16_rn(t[threadIdx.x][rr]);
    }
}

// transpose-pack 3 separate 512x512 sources stacked by z
__global__ void tpackz_kernel(const float* __restrict__ s0, const float* __restrict__ s1,
                              const float* __restrict__ s2,
                              __nv_bfloat16* __restrict__ dst)
{
    __shared__ float t[32][33];
    const int z = blockIdx.z;
    const float* s = (z == 0) ? s0 : (z == 1) ? s1 : s2;
    const int c0 = blockIdx.x * 32, r0 = blockIdx.y * 32;
#pragma unroll
    for (int i = 0; i < 4; i++) {
        int rr = threadIdx.y + i * 8;
        t[rr][threadIdx.x] = s[(size_t)(r0 + rr) * 512 + c0 + threadIdx.x];
    }
    __syncthreads();
#pragma unroll
    for (int i = 0; i < 4; i++) {
        int rr = threadIdx.y + i * 8;
        dst[(size_t)(z * 512 + c0 + rr) * 512 + r0 + threadIdx.x] =
            __float2bfloat16_rn(t[threadIdx.x][rr]);
    }
}

// ---------------- ptx helpers ----------------
__device__ __forceinline__ void cp16s(uint32_t saddr, const void* gmem) {
    asm volatile("cp.async.cg.shared.global [%0], [%1], 16;\n" :: "r"(saddr), "l"(gmem));
}
__device__ __forceinline__ void cp_commit() { asm volatile("cp.async.commit_group;\n"); }
__device__ __forceinline__ void cp_wait0()  { asm volatile("cp.async.wait_group 0;\n"); }
__device__ __forceinline__ void cp_wait1()  { asm volatile("cp.async.wait_group 1;\n"); }

__device__ __forceinline__ void mma_bf16(float c[4], const uint32_t a[4], const uint32_t b[2]) {
    asm volatile(
        "mma.sync.aligned.m16n8k16.row.col.f32.bf16.bf16.f32 "
        "{%0,%1,%2,%3}, {%4,%5,%6,%7}, {%8,%9}, {%0,%1,%2,%3};\n"
        : "+f"(c[0]), "+f"(c[1]), "+f"(c[2]), "+f"(c[3])
        : "r"(a[0]), "r"(a[1]), "r"(a[2]), "r"(a[3]), "r"(b[0]), "r"(b[1]));
}

__device__ __forceinline__ void ldsm_x4(uint32_t& r0, uint32_t& r1, uint32_t& r2, uint32_t& r3,
                                        uint32_t saddr) {
    asm volatile("ldmatrix.sync.aligned.m8n8.x4.shared.b16 {%0,%1,%2,%3}, [%4];"
                 : "=r"(r0), "=r"(r1), "=r"(r2), "=r"(r3) : "r"(saddr));
}
__device__ __forceinline__ void ldsm_x4_t(uint32_t& r0, uint32_t& r1, uint32_t& r2, uint32_t& r3,
                                          uint32_t saddr) {
    asm volatile("ldmatrix.sync.aligned.m8n8.x4.trans.shared.b16 {%0,%1,%2,%3}, [%4];"
                 : "=r"(r0), "=r"(r1), "=r"(r2), "=r"(r3) : "r"(saddr));
}

// ---------------- BF16 tensor-core GEMM (R9 shape: 128x128x64, 256 thr) -----
#define FLAG_RELU  1
#define FLAG_GATE  2
#define FLAG_WF32  4
#define FLAG_WBF16 8

#define BG_ROWB   144
#define BG_ASTG   18432
#define BG_SMEM_BYTES 73728

__global__ void __launch_bounds__(256)
bgemm_kernel(const __nv_bfloat16* __restrict__ A, int lda,
             const __nv_bfloat16* __restrict__ W, int K,
             const float* __restrict__ bias,
             const float* __restrict__ res,
             const float* __restrict__ gates,
             float* __restrict__ Cf, __nv_bfloat16* __restrict__ Cb,
             int ldc, int N, int flags)
{
    extern __shared__ char smc[];
    const uint32_t sb = (uint32_t)__cvta_generic_to_shared(smc);

    const int tid  = threadIdx.x;
    const int warp = tid >> 5;
    const int lane = tid & 31;
    const int r = lane >> 2;
    const int c = lane & 3;
    const int wm = warp >> 2;
    const int wn = warp & 3;
    const int m0 = blockIdx.y * 128, n0 = blockIdx.x * 128;

    float acc[4][4][4];
#pragma unroll
    for (int i = 0; i < 4; i++)
#pragma unroll
        for (int j = 0; j < 4; j++)
#pragma unroll
            for (int q = 0; q < 4; q++) acc[i][j][q] = 0.f;

    const int ntk = K >> 6;
    const __nv_bfloat16* Abase = A + (size_t)m0 * lda;
    const __nv_bfloat16* Bbase = W + (size_t)n0 * K;

    const uint32_t lmoff = (uint32_t)(lane & 15) * BG_ROWB + (uint32_t)(lane >> 4) * 16;

#define BG_LOAD(s, t) do {                                                      \
        const uint32_t ab = sb + (s) * BG_ASTG;                                 \
        const uint32_t bb = sb + 2 * BG_ASTG + (s) * BG_ASTG;                   \
        _Pragma("unroll")                                                       \
        for (int i_ = 0; i_ < 4; i_++) {                                        \
            const int ch = tid + i_ * 256;                                      \
            const int row = ch >> 3, c16 = ch & 7;                              \
            cp16s(ab + row * BG_ROWB + c16 * 16,                                \
                  Abase + (size_t)row * lda + (t) * 64 + c16 * 8);              \
            cp16s(bb + row * BG_ROWB + c16 * 16,                                \
                  Bbase + (size_t)row * K + (t) * 64 + c16 * 8);                \
        }                                                                       \
    } while (0)

    BG_LOAD(0, 0); cp_commit();
    if (ntk > 1) { BG_LOAD(1, 1); }
    cp_commit();

    for (int t = 0; t < ntk; t++) {
        cp_wait1();
        __syncthreads();
        const int s = t & 1;
        const uint32_t aS = sb + s * BG_ASTG + (uint32_t)(wm * 64) * BG_ROWB + lmoff;
        const uint32_t bS = sb + 2 * BG_ASTG + s * BG_ASTG + (uint32_t)(wn * 32) * BG_ROWB + lmoff;

#pragma unroll
        for (int ks = 0; ks < 4; ks++) {
            const uint32_t kb = ks * 32;
            uint32_t af[4][4];
#pragma unroll
            for (int mi = 0; mi < 4; mi++)
                ldsm_x4(af[mi][0], af[mi][1], af[mi][2], af[mi][3],
                        aS + (uint32_t)(mi * 16) * BG_ROWB + kb);
            uint32_t b00, b01, b02, b03, b10, b11, b12, b13;
            ldsm_x4(b00, b01, b02, b03, bS + kb);
            ldsm_x4(b10, b11, b12, b13, bS + 16u * BG_ROWB + kb);
            uint32_t bf4[4][2] = {{b00, b02}, {b01, b03}, {b10, b12}, {b11, b13}};
#pragma unroll
            for (int mi = 0; mi < 4; mi++)
#pragma unroll
                for (int nj = 0; nj < 4; nj++)
                    mma_bf16(acc[mi][nj], af[mi], bf4[nj]);
        }
        __syncthreads();
        if (t + 2 < ntk) { BG_LOAD(s, t + 2); }
        cp_commit();
    }

    // ---------------- epilogue ----------------
    const bool do_relu = (flags & FLAG_RELU) != 0;
    const bool do_gate = (flags & FLAG_GATE) != 0;
    const bool wf32    = (flags & FLAG_WF32) != 0;
    const bool wbf16   = (flags & FLAG_WBF16) != 0;
    const int  eblk    = n0 >> 11;

#pragma unroll
    for (int mi = 0; mi < 4; mi++) {
#pragma unroll
        for (int half = 0; half < 2; half++) {
            const int mrow = m0 + wm * 64 + mi * 16 + r + half * 8;
            const float rsv = do_gate ? gates[(size_t)mrow * E_ + eblk] : 1.f;
            const size_t rowbase = (size_t)mrow * ldc;
#pragma unroll
            for (int nj = 0; nj < 4; nj++) {
                const int ncol = n0 + wn * 32 + nj * 8 + 2 * c;
                float v0 = acc[mi][nj][half * 2 + 0];
                float v1 = acc[mi][nj][half * 2 + 1];
                if (bias) { v0 += bias[ncol]; v1 += bias[ncol + 1]; }
                if (do_relu) { v0 = fmaxf(v0, 0.f); v1 = fmaxf(v1, 0.f); }
                v0 *= rsv; v1 *= rsv;
                if (res) { v0 += res[rowbase + ncol]; v1 += res[rowbase + ncol + 1]; }
                if (wf32)  *(float2*)&Cf[rowbase + ncol] = make_float2(v0, v1);
                if (wbf16) *(__nv_bfloat162*)&Cb[rowbase + ncol] = __floats2bfloat162_rn(v0, v1);
            }
        }
    }
#undef BG_LOAD
}

static inline void bgemm(const __nv_bfloat16* A, int lda, const __nv_bfloat16* W, int K,
                         const float* bias, const float* res, const float* gates,
                         float* Cf, __nv_bfloat16* Cb, int ldc, int M, int N, int flags)
{
    dim3 grid(N / 128, M / 128);
    bgemm_kernel<<<grid, 256, BG_SMEM_BYTES>>>(A, lda, W, K, bias, res, gates, Cf, Cb, ldc, N, flags);
}

// ---------------- flash attention: full bf16, 128 queries/CTA, 256 threads --
// Q/K/V bf16 from producer GEMMs. m16n8k16 mma throughout. Double-buffered
// 64-key KV tiles; causal CTAs remapped heavy-first (LPT). Scale 1/8 applied
// to S accumulators (exact power of 2).
// smem layout (bytes): stage s in [s*18432, +18432): K 64x144, V at +9216.
// Q (128x144 = 18432 B) unioned with P (8 warps x 16 x 144 = 18432 B) at 36864.
#define AT_ROWB 144
#define AT_KSTG 9216
#define AT_STGB 18432
#define AT_QP   36864
#define ATTN_SMEM_BYTES 55296

template<bool CAUSAL>
__global__ void __launch_bounds__(256)
fattn_kernel(const __nv_bfloat16* __restrict__ Q, int q_ld,
             const __nv_bfloat16* __restrict__ Kp, const __nv_bfloat16* __restrict__ Vp,
             int kv_ld, __nv_bfloat16* __restrict__ Ob, int Sk)
{
    extern __shared__ char smb[];
    const uint32_t sb = (uint32_t)__cvta_generic_to_shared(smb);

    const int b = blockIdx.z, head = blockIdx.y;
    const int qt = CAUSAL ? (gridDim.x - 1 - blockIdx.x) : blockIdx.x;  // LPT
    const int tid  = threadIdx.x;
    const int w    = tid >> 5;
    const int lane = tid & 31;
    const int r = lane >> 2;
    const int c = lane & 3;
    const int wbase = w * 16;

    const uint32_t lmoff = (uint32_t)(lane & 15) * AT_ROWB + (uint32_t)(lane >> 4) * 16;

    // KV tile loader: K 512 chunks + V 512 chunks, 256 threads -> 4 iters
#define ATT_LOAD(s, t) do {                                                      \
        const __nv_bfloat16* Kg_ = Kp + ((size_t)b * Sk + (t) * 64) * kv_ld + head * DH_; \
        const __nv_bfloat16* Vg_ = Vp + ((size_t)b * Sk + (t) * 64) * kv_ld + head * DH_; \
        const uint32_t kb_ = sb + (s) * AT_STGB;                                 \
        const uint32_t vb_ = kb_ + AT_KSTG;                                      \
        _Pragma("unroll")                                                        \
        for (int i_ = 0; i_ < 2; i_++) {                                         \
            const int ch = tid + i_ * 256;                                       \
            const int row = ch >> 3, c16 = ch & 7;                               \
            cp16s(kb_ + row * AT_ROWB + c16 * 16, Kg_ + (size_t)row * kv_ld + c16 * 8); \
            cp16s(vb_ + row * AT_ROWB + c16 * 16, Vg_ + (size_t)row * kv_ld + c16 * 8); \
        }                                                                        \
    } while (0)

    // ---- stage Q (128 rows x 64 bf16) ----
    const __nv_bfloat16* Qg = Q + ((size_t)b * S_ + qt * 128) * q_ld + head * DH_;
#pragma unroll
    for (int i = 0; i < 4; i++) {
        const int ch = tid + i * 256;      // 1024 chunks
        const int row = ch >> 3, c16 = ch & 7;
        cp16s(sb + AT_QP + row * AT_ROWB + c16 * 16, Qg + (size_t)row * q_ld + c16 * 8);
    }
    cp_commit();
    ATT_LOAD(0, 0);
    cp_commit();
    cp_wait1();           // Q group complete
    __syncthreads();      // visible to all

    // Q A-fragments (m16n8k16): 4 k-steps of 16
    uint32_t aq[4][4];
    {
        const uint32_t qS = sb + AT_QP + (uint32_t)wbase * AT_ROWB + lmoff;
#pragma unroll
        for (int ks = 0; ks < 4; ks++)
            ldsm_x4(aq[ks][0], aq[ks][1], aq[ks][2], aq[ks][3], qS + ks * 32);
    }

    float accO[8][4];
#pragma unroll
    for (int nj = 0; nj < 8; nj++)
#pragma unroll
        for (int q = 0; q < 4; q++) accO[nj][q] = 0.f;
    float mrow[2] = {-1e30f, -1e30f};
    float lrow[2] = {0.f, 0.f};

    const int ntiles = CAUSAL ? (2 * qt + 2) : (Sk >> 6);

    for (int t = 0; t < ntiles; t++) {
        __syncthreads();                   // everyone done with buffer being refilled / Q read
        if (t + 1 < ntiles) {
            ATT_LOAD((t + 1) & 1, t + 1);
            cp_commit();
            cp_wait1();
        } else {
            cp_wait0();
        }
        __syncthreads();

        const uint32_t kS = sb + (uint32_t)((t & 1) * AT_STGB) + lmoff;
        const uint32_t vS = sb + (uint32_t)((t & 1) * AT_STGB) + AT_KSTG;

        // ---- S = Q K^T (bf16 mma, K plain ldmatrix: [key][d] k-contig) ----
        float accS[8][4];
#pragma unroll
        for (int nj = 0; nj < 8; nj++)
#pragma unroll
            for (int q = 0; q < 4; q++) accS[nj][q] = 0.f;
#pragma unroll
        for (int ks = 0; ks < 4; ks++) {
            uint32_t bfr[8][2];
#pragma unroll
            for (int g = 0; g < 4; g++) {
                uint32_t q0, q1, q2, q3;
                ldsm_x4(q0, q1, q2, q3, kS + (uint32_t)(g * 16) * AT_ROWB + ks * 32);
                bfr[g * 2 + 0][0] = q0; bfr[g * 2 + 0][1] = q2;
                bfr[g * 2 + 1][0] = q1; bfr[g * 2 + 1][1] = q3;
            }
#pragma unroll
            for (int nj = 0; nj < 8; nj++)
                mma_bf16(accS[nj], aq[ks], bfr[nj]);
        }
        // scale 1/sqrt(64) (exact)
#pragma unroll
        for (int nj = 0; nj < 8; nj++)
#pragma unroll
            for (int q = 0; q < 4; q++) accS[nj][q] *= 0.125f;

        // ---- causal mask (last two tiles: t = 2qt, 2qt+1) ----
        if (CAUSAL && t >= 2 * qt) {
            const int koff = (t - 2 * qt) * 64;
#pragma unroll
            for (int nj = 0; nj < 8; nj++) {
                const int key0 = koff + nj * 8 + 2 * c;
#pragma unroll
                for (int q = 0; q < 4; q++) {
                    const int key  = key0 + (q & 1);
                    const int qrow = wbase + r + (q >> 1) * 8;
                    if (key > qrow) accS[nj][q] = -1e30f;
                }
            }
        }

        // ---- online softmax; write P as bf16 pairs ----
        const uint32_t pwBase = sb + AT_QP + (uint32_t)w * 2304;
#pragma unroll
        for (int hh = 0; hh < 2; hh++) {
            float vmax = -1e30f;
#pragma unroll
            for (int nj = 0; nj < 8; nj++)
                vmax = fmaxf(vmax, fmaxf(accS[nj][2 * hh], accS[nj][2 * hh + 1]));
            vmax = fmaxf(vmax, __shfl_xor_sync(0xffffffffu, vmax, 1));
            vmax = fmaxf(vmax, __shfl_xor_sync(0xffffffffu, vmax, 2));
            const float mnew = fmaxf(mrow[hh], vmax);
            const float corr = __expf(mrow[hh] - mnew);
            float psum = 0.f;
            const uint32_t pw = pwBase + (uint32_t)(r + 8 * hh) * AT_ROWB + (uint32_t)(4 * c);
#pragma unroll
            for (int nj = 0; nj < 8; nj++) {
                const float p0 = __expf(accS[nj][2 * hh]     - mnew);
                const float p1 = __expf(accS[nj][2 * hh + 1] - mnew);
                psum += p0 + p1;
                __nv_bfloat162 pb = __floats2bfloat162_rn(p0, p1);
                asm volatile("st.shared.b32 [%0], %1;" :: "r"(pw + nj * 16), "r"(*(uint32_t*)&pb));
                accO[nj][2 * hh]     *= corr;
                accO[nj][2 * hh + 1] *= corr;
            }
            psum += __shfl_xor_sync(0xffffffffu, psum, 1);
            psum += __shfl_xor_sync(0xffffffffu, psum, 2);
            lrow[hh] = lrow[hh] * corr + psum;
            mrow[hh] = mnew;
        }
        __syncwarp();

        // ---- O += P V (P plain A-frag; V via ldmatrix.trans: [key][d]) ----
        const uint32_t pS = pwBase + lmoff;
#pragma unroll
        for (int ks = 0; ks < 4; ks++) {   // key steps of 16
            uint32_t ap[4];
            ldsm_x4(ap[0], ap[1], ap[2], ap[3], pS + ks * 32);
            uint32_t bfr[8][2];
#pragma unroll
            for (int g = 0; g < 4; g++) {  // d blocks of 16
                uint32_t q0, q1, q2, q3;
                ldsm_x4_t(q0, q1, q2, q3,
                          vS + (uint32_t)(ks * 16 + (lane & 15)) * AT_ROWB
                             + (uint32_t)(g * 32) + (uint32_t)(lane >> 4) * 16);
                bfr[g * 2 + 0][0] = q0; bfr[g * 2 + 0][1] = q1;
                bfr[g * 2 + 1][0] = q2; bfr[g * 2 + 1][1] = q3;
            }
#pragma unroll
            for (int nj = 0; nj < 8; nj++)
                mma_bf16(accO[nj], ap, bfr[nj]);
        }
    }
#undef ATT_LOAD

    const float inv0 = 1.f / lrow[0];
    const float inv1 = 1.f / lrow[1];
    const int row0 = qt * 128 + wbase + r;
    __nv_bfloat16* Obp = Ob + ((size_t)b * S_ + row0) * D_ + head * DH_;
#pragma unroll
    for (int nj = 0; nj < 8; nj++) {
        const int col = nj * 8 + 2 * c;
        *(__nv_bfloat162*)&Obp[col] = __floats2bfloat162_rn(accO[nj][0] * inv0, accO[nj][1] * inv0);
        *(__nv_bfloat162*)&Obp[(size_t)8 * D_ + col] =
            __floats2bfloat162_rn(accO[nj][2] * inv1, accO[nj][3] * inv1);
    }
}

// ---------------- LayerNorm kernels ----------------
__global__ void __launch_bounds__(256)
ln_kernel(const float* __restrict__ a,
          const float* __restrict__ g, const float* __restrict__ be,
          float* __restrict__ out, __nv_bfloat16* __restrict__ outb)
{
    const int row = blockIdx.x;
    const int t = threadIdx.x;
    const size_t base = (size_t)row * D_;
    float v0 = a[base + t];
    float v1 = a[base + t + 256];

    float s = v0 + v1, ss = v0 * v0 + v1 * v1;
    const int lane = t & 31, w = t >> 5;
    __shared__ float shs[8], shss[8];
#pragma unroll
    for (int off = 16; off; off >>= 1) {
        s  += __shfl_down_sync(0xffffffffu, s,  off);
        ss += __shfl_down_sync(0xffffffffu, ss, off);
    }
    if (lane == 0) { shs[w] = s; shss[w] = ss; }
    __syncthreads();
    __shared__ float mean_sh, inv_sh;
    if (t == 0) {
        float S = 0.f, SS = 0.f;
#pragma unroll
        for (int i = 0; i < 8; i++) { S += shs[i]; SS += shss[i]; }
        float mean = S * (1.f / (float)D_);
        float var  = SS * (1.f / (float)D_) - mean * mean;
        mean_sh = mean;
        inv_sh  = rsqrtf(var + EPS_);
    }
    __syncthreads();
    float mean = mean_sh, inv = inv_sh;
    float o0 = (v0 - mean) * inv * g[t]       + be[t];
    float o1 = (v1 - mean) * inv * g[t + 256] + be[t + 256];
    out[base + t]       = o0;
    out[base + t + 256] = o1;
    if (outb) {
        outb[base + t]       = __float2bfloat16_rn(o0);
        outb[base + t + 256] = __float2bfloat16_rn(o1);
    }
}

__global__ void __launch_bounds__(256)
ln3_kernel(const float* __restrict__ xb, const float* __restrict__ y,
           const float* __restrict__ gates, const float* __restrict__ b2,
           const float* __restrict__ g, const float* __restrict__ be,
           float* __restrict__ out)
{
    const int row = blockIdx.x;
    const int t = threadIdx.x;
    const size_t base = (size_t)row * D_;
    const float ga0 = gates[(size_t)row * E_ + 0];
    const float ga1 = gates[(size_t)row * E_ + 1];
    const float ga2 = gates[(size_t)row * E_ + 2];
    const float ga3 = gates[(size_t)row * E_ + 3];
    float gb0 = ga0 * b2[t]        + ga1 * b2[D_ + t]        + ga2 * b2[2*D_ + t]        + ga3 * b2[3*D_ + t];
    float gb1 = ga0 * b2[t + 256]  + ga1 * b2[D_ + t + 256]  + ga2 * b2[2*D_ + t + 256]  + ga3 * b2[3*D_ + t + 256];
    float v0 = xb[base + t]       + y[base + t]       + gb0;
    float v1 = xb[base + t + 256] + y[base + t + 256] + gb1;

    float s = v0 + v1, ss = v0 * v0 + v1 * v1;
    const int lane = t & 31, w = t >> 5;
    __shared__ float shs[8], shss[8];
#pragma unroll
    for (int off = 16; off; off >>= 1) {
        s  += __shfl_down_sync(0xffffffffu, s,  off);
        ss += __shfl_down_sync(0xffffffffu, ss, off);
    }
    if (lane == 0) { shs[w] = s; shss[w] = ss; }
    __syncthreads();
    __shared__ float mean_sh, inv_sh;
    if (t == 0) {
        float S = 0.f, SS = 0.f;
#pragma unroll
        for (int i = 0; i < 8; i++) { S += shs[i]; SS += shss[i]; }
        float mean = S * (1.f / (float)D_);
        float var  = SS * (1.f / (float)D_) - mean * mean;
        mean_sh = mean;
        inv_sh  = rsqrtf(var + EPS_);
    }
    __syncthreads();
    float mean = mean_sh, inv = inv_sh;
    out[base + t]       = (v0 - mean) * inv * g[t]       + be[t];
    out[base + t + 256] = (v1 - mean) * inv * g[t + 256] + be[t + 256];
}

// ---------------- gate ----------------
__global__ void __launch_bounds__(256)
gate_kernel(const float* __restrict__ x, const float* __restrict__ gw,
            const float* __restrict__ gb)
{
    const int warp = (blockIdx.x * blockDim.x + threadIdx.x) >> 5;
    const int lane = threadIdx.x & 31;
    if (warp >= BSROWS) return;
    const float* xr = x + (size_t)warp * D_;
    float a0 = 0.f, a1 = 0.f, a2 = 0.f, a3 = 0.f;
    for (int d = lane; d < D_; d += 32) {
        float xv = xr[d];
        const float* wr = gw + (size_t)d * E_;
        a0 += xv * wr[0]; a1 += xv * wr[1]; a2 += xv * wr[2]; a3 += xv * wr[3];
    }
#pragma unroll
    for (int off = 16; off; off >>= 1) {
        a0 += __shfl_down_sync(0xffffffffu, a0, off);
        a1 += __shfl_down_sync(0xffffffffu, a1, off);
        a2 += __shfl_down_sync(0xffffffffu, a2, off);
        a3 += __shfl_down_sync(0xffffffffu, a3, off);
    }
    if (lane == 0) {
        float l0 = a0 + gb[0], l1 = a1 + gb[1], l2 = a2 + gb[2], l3 = a3 + gb[3];
        float mx = fmaxf(fmaxf(l0, l1), fmaxf(l2, l3));
        float e0 = __expf(l0 - mx), e1 = __expf(l1 - mx);
        float e2 = __expf(l2 - mx), e3 = __expf(l3 - mx);
        float si = 1.f / (e0 + e1 + e2 + e3);
        float p0 = e0 * si, p1 = e1 * si, p2 = e2 * si, p3 = e3 * si;
        float* gp = g_gates + (size_t)warp * E_;
        gp[0] = p0; gp[1] = p1; gp[2] = p2; gp[3] = p3;
        atomicAdd(&g_gsum[0], p0);
        atomicAdd(&g_gsum[1], p1);
        atomicAdd(&g_gsum[2], p2);
        atomicAdd(&g_gsum[3], p3);
    }
}

// ---------------- host orchestration ----------------
extern "C" void kernel_launch(void* const* d_in, const int* in_sizes, int n_in,
                              void* d_out, int out_size)
{
    const float* x      = (const float*)d_in[0];
    const float* cross  = (const float*)d_in[1];
    const float* sa_wq  = (const float*)d_in[2];
    const float* sa_bq  = (const float*)d_in[3];
    const float* sa_wk  = (const float*)d_in[4];
    const float* sa_bk  = (const float*)d_in[5];
    const float* sa_wv  = (const float*)d_in[6];
    const float* sa_bv  = (const float*)d_in[7];
    const float* sa_wo  = (const float*)d_in[8];
    const float* sa_bo  = (const float*)d_in[9];
    const float* ca_wq  = (const float*)d_in[10];
    const float* ca_bq  = (const float*)d_in[11];
    const float* ca_wk  = (const float*)d_in[12];
    const float* ca_bk  = (const float*)d_in[13];
    const float* ca_wv  = (const float*)d_in[14];
    const float* ca_bv  = (const float*)d_in[15];
    const float* ca_wo  = (const float*)d_in[16];
    const float* ca_bo  = (const float*)d_in[17];
    const float* gate_w = (const float*)d_in[18];
    const float* gate_b = (const float*)d_in[19];
    const float* exp_w1 = (const float*)d_in[20];
    const float* exp_b1 = (const float*)d_in[21];
    const float* exp_w2 = (const float*)d_in[22];
    const float* exp_b2 = (const float*)d_in[23];
    const float* n1_g   = (const float*)d_in[24];
    const float* n1_b   = (const float*)d_in[25];
    const float* n2_g   = (const float*)d_in[26];
    const float* n2_b   = (const float*)d_in[27];
    const float* n3_g   = (const float*)d_in[28];
    const float* n3_b   = (const float*)d_in[29];
    float* out = (float*)d_out;

    float *pre, *xa, *xb, *y, *gates, *bqkv, *bcakv;
    __nv_bfloat16 *qkvbf, *attbf, *xabf, *xbbf, *hbf, *xbf, *crbf;
    __nv_bfloat16 *wqkvt, *wsaot, *wcaqt, *wcakvt, *wcaot, *w1t, *w2t;
    cudaGetSymbolAddress((void**)&qkvbf,  g_qkvbf);
    cudaGetSymbolAddress((void**)&pre,    g_pre);
    cudaGetSymbolAddress((void**)&xa,     g_xa);
    cudaGetSymbolAddress((void**)&xb,     g_xb);
    cudaGetSymbolAddress((void**)&y,      g_y);
    cudaGetSymbolAddress((void**)&gates,  g_gates);
    cudaGetSymbolAddress((void**)&bqkv,   g_bqkv);
    cudaGetSymbolAddress((void**)&bcakv,  g_bcakv);
    cudaGetSymbolAddress((void**)&attbf,  g_attbf);
    cudaGetSymbolAddress((void**)&xabf,   g_xabf);
    cudaGetSymbolAddress((void**)&xbbf,   g_xbbf);
    cudaGetSymbolAddress((void**)&hbf,    g_hbf);
    cudaGetSymbolAddress((void**)&xbf,    g_xbf);
    cudaGetSymbolAddress((void**)&crbf,   g_crbf);
    cudaGetSymbolAddress((void**)&wqkvt,  g_wqkvt);
    cudaGetSymbolAddress((void**)&wsaot,  g_wsaot);
    cudaGetSymbolAddress((void**)&wcaqt,  g_wcaqt);
    cudaGetSymbolAddress((void**)&wcakvt, g_wcakvt);
    cudaGetSymbolAddress((void**)&wcaot,  g_wcaot);
    cudaGetSymbolAddress((void**)&w1t,    g_w1t);
    cudaGetSymbolAddress((void**)&w2t,    g_w2t);

    static bool attr_done = false;
    if (!attr_done) {
        cudaFuncSetAttribute(fattn_kernel<true>,
                             cudaFuncAttributeMaxDynamicSharedMemorySize, ATTN_SMEM_BYTES);
        cudaFuncSetAttribute(fattn_kernel<false>,
                             cudaFuncAttributeMaxDynamicSharedMemorySize, ATTN_SMEM_BYTES);
        cudaFuncSetAttribute(bgemm_kernel,
                             cudaFuncAttributeMaxDynamicSharedMemorySize, BG_SMEM_BYTES);
        attr_done = true;
    }

    dim3 tb(32, 8);

    // ---- prep ----
    zero_gsum_kernel<<<1, 32>>>();
    cvtbf_kernel<<<(BSROWS*D_/4 + 255)/256, 256>>>(x, xbf, BSROWS*D_/4);
    cvtbf_kernel<<<(BTROWS*D_/4 + 255)/256, 256>>>(cross, crbf, BTROWS*D_/4);
    tpackz_kernel<<<dim3(16,16,3), tb>>>(sa_wq, sa_wk, sa_wv, wqkvt);
    pack3f_kernel<<<2, 256>>>(sa_bq, sa_bk, sa_bv, bqkv);
    bgemm(xbf, 512, wqkvt, 512, bqkv, nullptr, nullptr, nullptr, qkvbf, 1536,
          BSROWS, 1536, FLAG_WBF16);

    tpack3_kernel<<<dim3(16,16,1), tb>>>(sa_wo, 512, 0, wsaot, 512, 0, 0, 0, 0);
    tpack3_kernel<<<dim3(16,16,1), tb>>>(ca_wq, 512, 0, wcaqt, 512, 0, 0, 0, 0);
    tpackz_kernel<<<dim3(16,16,2), tb>>>(ca_wk, ca_wv, nullptr, wcakvt);
    tpack3_kernel<<<dim3(16,16,1), tb>>>(ca_wo, 512, 0, wcaot, 512, 0, 0, 0, 0);
    tpack3_kernel<<<dim3(64,16,4), tb>>>(exp_w1, DF_, (size_t)D_*DF_, w1t, 512, 0, 0, DF_, 0);
    tpack3_kernel<<<dim3(16,64,4), tb>>>(exp_w2, 512, (size_t)DF_*D_, w2t, 8192, 0, 0, 0, DF_);
    pack3f_kernel<<<2, 256>>>(ca_bk, ca_bv, nullptr, bcakv);

    // ---- self-attention block ----
    fattn_kernel<true><<<dim3(S_/128, H_, B_), 256, ATTN_SMEM_BYTES>>>(
        qkvbf, 1536, qkvbf + 512, qkvbf + 1024, 1536, attbf, S_);
    bgemm(attbf, 512, wsaot, 512, sa_bo, /*res=*/x, nullptr, pre, nullptr, 512,
          BSROWS, 512, FLAG_WF32);
    ln_kernel<<<BSROWS, 256>>>(pre, n1_g, n1_b, xa, xabf);

    // ---- cross-attention block ----
    __nv_bfloat16* qc  = qkvbf;                          // [16384][512]
    __nv_bfloat16* kvc = qkvbf + (size_t)BSROWS * 512;   // [8192][1024]
    bgemm(xabf, 512, wcaqt, 512, ca_bq, nullptr, nullptr, nullptr, qc, 512,
          BSROWS, 512, FLAG_WBF16);
    bgemm(crbf, 512, wcakvt, 512, bcakv, nullptr, nullptr, nullptr, kvc, 1024,
          BTROWS, 1024, FLAG_WBF16);
    fattn_kernel<false><<<dim3(S_/128, H_, B_), 256, ATTN_SMEM_BYTES>>>(
        qc, 512, kvc, kvc + 512, 1024, attbf, T_);
    bgemm(attbf, 512, wcaot, 512, ca_bo, /*res=*/xa, nullptr, pre, nullptr, 512,
          BSROWS, 512, FLAG_WF32);
    ln_kernel<<<BSROWS, 256>>>(pre, n2_g, n2_b, xb, xbbf);

    // ---- MoE (monolithic) ----
    gate_kernel<<<(BSROWS * 32 + 255) / 256, 256>>>(xb, gate_w, gate_b);
    aux_kernel<<<1, 1>>>(out, out_size);
    bgemm(xbbf, 512, w1t, 512, exp_b1, nullptr, gates, nullptr, hbf, 8192,
          BSROWS, 8192, FLAG_RELU | FLAG_GATE | FLAG_WBF16);
    bgemm(hbf, 8192, w2t, 8192, nullptr, nullptr, nullptr, y, nullptr, 512,
          BSROWS, 512, FLAG_WF32);
    ln3_kernel<<<BSROWS, 256>>>(xb, y, gates, exp_b2, n3_g, n3_b, out);
}

// round 16
// speedup vs baseline: 1.0422x; 1.0422x over previous
#include <cuda_runtime.h>
#include <cuda_bf16.h>
#include <cstdint>

// Problem constants
#define B_  16
#define S_  1024
#define T_  512
#define D_  512
#define H_  8
#define DH_ 64
#define DF_ 2048
#define E_  4
#define BSROWS (B_*S_)    // 16384
#define BTROWS (B_*T_)    // 8192
#define EPS_ 1e-5f

// ---------------- scratch (static __device__ — no allocation) ----------------
__device__ float          g_qkv  [BSROWS*1536];
__device__ __nv_bfloat16  g_attbf[BSROWS*D_];
__device__ float          g_pre  [BSROWS*D_];
__device__ float          g_xa   [BSROWS*D_];
__device__ __nv_bfloat16  g_xabf [BSROWS*D_];
__device__ float          g_xb   [BSROWS*D_];
__device__ __nv_bfloat16  g_xbbf [BSROWS*D_];
__device__ float          g_y    [BSROWS*D_];
__device__ __nv_bfloat16  g_hbf  [(size_t)BSROWS*E_*DF_];
__device__ __nv_bfloat16  g_xbf  [BSROWS*D_];
__device__ __nv_bfloat16  g_crbf [BTROWS*D_];
__device__ float          g_gates[BSROWS*E_];
__device__ float          g_gsum [E_];
// packed / transposed weights (bf16, [N][K] k-contiguous)
__device__ __nv_bfloat16  g_wqkvt [1536*D_];
__device__ float          g_bqkv  [1536];
__device__ __nv_bfloat16  g_wsaot [D_*D_];
__device__ __nv_bfloat16  g_wcaqt [D_*D_];
__device__ __nv_bfloat16  g_wcakvt[1024*D_];
__device__ float          g_bcakv [1024];
__device__ __nv_bfloat16  g_wcaot [D_*D_];
__device__ __nv_bfloat16  g_w1t   [(size_t)E_*DF_*D_];      // [8192][512]
__device__ __nv_bfloat16  g_w2t   [(size_t)D_*E_*DF_];      // [512][8192]

// ---------------- tiny utility kernels ----------------
__global__ void zero_gsum_kernel() {
    if (threadIdx.x < E_) g_gsum[threadIdx.x] = 0.f;
}

__global__ void aux_kernel(float* out, int out_size) {
    float s = 0.f;
#pragma unroll
    for (int e = 0; e < E_; e++) {
        float mn = g_gsum[e] * (1.f / (float)BSROWS);
        s += mn * mn;
    }
    if (out_size > BSROWS * D_) out[BSROWS * D_] = (float)E_ * s;
}

__global__ void pack3f_kernel(const float* __restrict__ a, const float* __restrict__ b,
                              const float* __restrict__ c, float* __restrict__ d)
{
    int i = blockIdx.x * blockDim.x + threadIdx.x;
    if (i < 512) {
        d[i] = a[i];
        if (b) d[512 + i]  = b[i];
        if (c) d[1024 + i] = c[i];
    }
}

__global__ void cvtbf_kernel(const float* __restrict__ s, __nv_bfloat16* __restrict__ d, int n4) {
    int i = blockIdx.x * blockDim.x + threadIdx.x;
    if (i < n4) {
        float4 f = ((const float4*)s)[i];
        __nv_bfloat162* dd = (__nv_bfloat162*)d + i * 2;
        dd[0] = __floats2bfloat162_rn(f.x, f.y);
        dd[1] = __floats2bfloat162_rn(f.z, f.w);
    }
}

// transpose-pack with z batching over a single contiguous src
__global__ void tpack3_kernel(const float* __restrict__ src, int srcCols, size_t srcZ,
                              __nv_bfloat16* __restrict__ dst, int dstLd,
                              int dRow0, int dCol0, int zRowStep, int zColStep)
{
    __shared__ float t[32][33];
    const int z = blockIdx.z;
    const int c0 = blockIdx.x * 32, r0 = blockIdx.y * 32;
    const float* s = src + (size_t)z * srcZ;
    const int row0 = dRow0 + z * zRowStep;
    const int col0 = dCol0 + z * zColStep;
#pragma unroll
    for (int i = 0; i < 4; i++) {
        int rr = threadIdx.y + i * 8;
        t[rr][threadIdx.x] = s[(size_t)(r0 + rr) * srcCols + c0 + threadIdx.x];
    }
    __syncthreads();
#pragma unroll
    for (int i = 0; i < 4; i++) {
        int rr = threadIdx.y + i * 8;
        dst[(size_t)(row0 + c0 + rr) * dstLd + col0 + r0 + threadIdx.x] =
            __float2bfloat16_rn(t[threadIdx.x][rr]);
    }
}

// transpose-pack 3 separate 512x512 sources stacked by z
__global__ void tpackz_kernel(const float* __restrict__ s0, const float* __restrict__ s1,
                              const float* __restrict__ s2,
                              __nv_bfloat16* __restrict__ dst)
{
    __shared__ float t[32][33];
    const int z = blockIdx.z;
    const float* s = (z == 0) ? s0 : (z == 1) ? s1 : s2;
    const int c0 = blockIdx.x * 32, r0 = blockIdx.y * 32;
#pragma unroll
    for (int i = 0; i < 4; i++) {
        int rr = threadIdx.y + i * 8;
        t[rr][threadIdx.x] = s[(size_t)(r0 + rr) * 512 + c0 + threadIdx.x];
    }
    __syncthreads();
#pragma unroll
    for (int i = 0; i < 4; i++) {
        int rr = threadIdx.y + i * 8;
        dst[(size_t)(z * 512 + c0 + rr) * 512 + r0 + threadIdx.x] =
            __float2bfloat16_rn(t[threadIdx.x][rr]);
    }
}

// ---------------- ptx helpers ----------------
__device__ __forceinline__ uint32_t f2tf32(float f) {
    uint32_t u;
    asm volatile("cvt.rna.tf32.f32 %0, %1;\n" : "=r"(u) : "f"(f));
    return u;
}
__device__ __forceinline__ void cp16(void* smem, const void* gmem) {
    uint32_t s = (uint32_t)__cvta_generic_to_shared(smem);
    asm volatile("cp.async.cg.shared.global [%0], [%1], 16;\n" :: "r"(s), "l"(gmem));
}
__device__ __forceinline__ void cp16s(uint32_t saddr, const void* gmem) {
    asm volatile("cp.async.cg.shared.global [%0], [%1], 16;\n" :: "r"(saddr), "l"(gmem));
}
__device__ __forceinline__ void cp_commit() { asm volatile("cp.async.commit_group;\n"); }
__device__ __forceinline__ void cp_wait0()  { asm volatile("cp.async.wait_group 0;\n"); }
__device__ __forceinline__ void cp_wait1()  { asm volatile("cp.async.wait_group 1;\n"); }

__device__ __forceinline__ void mma_tf32(float c[4], const uint32_t a[4], const uint32_t b[2]) {
    asm volatile(
        "mma.sync.aligned.m16n8k8.row.col.f32.tf32.tf32.f32 "
        "{%0,%1,%2,%3}, {%4,%5,%6,%7}, {%8,%9}, {%0,%1,%2,%3};\n"
        : "+f"(c[0]), "+f"(c[1]), "+f"(c[2]), "+f"(c[3])
        : "r"(a[0]), "r"(a[1]), "r"(a[2]), "r"(a[3]), "r"(b[0]), "r"(b[1]));
}

__device__ __forceinline__ void mma_bf16(float c[4], const uint32_t a[4], const uint32_t b[2]) {
    asm volatile(
        "mma.sync.aligned.m16n8k16.row.col.f32.bf16.bf16.f32 "
        "{%0,%1,%2,%3}, {%4,%5,%6,%7}, {%8,%9}, {%0,%1,%2,%3};\n"
        : "+f"(c[0]), "+f"(c[1]), "+f"(c[2]), "+f"(c[3])
        : "r"(a[0]), "r"(a[1]), "r"(a[2]), "r"(a[3]), "r"(b[0]), "r"(b[1]));
}

__device__ __forceinline__ void ldsm_x4(uint32_t& r0, uint32_t& r1, uint32_t& r2, uint32_t& r3,
                                        uint32_t saddr) {
    asm volatile("ldmatrix.sync.aligned.m8n8.x4.shared.b16 {%0,%1,%2,%3}, [%4];"
                 : "=r"(r0), "=r"(r1), "=r"(r2), "=r"(r3) : "r"(saddr));
}

// ---------------- BF16 tensor-core GEMM (R9 shape: 128x128x64, 256 thr) -----
#define FLAG_RELU  1
#define FLAG_GATE  2
#define FLAG_WF32  4
#define FLAG_WBF16 8
#define FLAG_WTF32 16

#define BG_ROWB   144
#define BG_ASTG   18432
#define BG_SMEM_BYTES 73728

__global__ void __launch_bounds__(256)
bgemm_kernel(const __nv_bfloat16* __restrict__ A, int lda,
             const __nv_bfloat16* __restrict__ W, int K,
             const float* __restrict__ bias,
             const float* __restrict__ res,
             const float* __restrict__ gates,
             float* __restrict__ Cf, __nv_bfloat16* __restrict__ Cb,
             int ldc, int N, int flags)
{
    extern __shared__ char smc[];
    const uint32_t sb = (uint32_t)__cvta_generic_to_shared(smc);

    const int tid  = threadIdx.x;
    const int warp = tid >> 5;
    const int lane = tid & 31;
    const int r = lane >> 2;
    const int c = lane & 3;
    const int wm = warp >> 2;
    const int wn = warp & 3;
    const int m0 = blockIdx.y * 128, n0 = blockIdx.x * 128;

    float acc[4][4][4];
#pragma unroll
    for (int i = 0; i < 4; i++)
#pragma unroll
        for (int j = 0; j < 4; j++)
#pragma unroll
            for (int q = 0; q < 4; q++) acc[i][j][q] = 0.f;

    const int ntk = K >> 6;
    const __nv_bfloat16* Abase = A + (size_t)m0 * lda;
    const __nv_bfloat16* Bbase = W + (size_t)n0 * K;

    const uint32_t lmoff = (uint32_t)(lane & 15) * BG_ROWB + (uint32_t)(lane >> 4) * 16;

#define BG_LOAD(s, t) do {                                                      \
        const uint32_t ab = sb + (s) * BG_ASTG;                                 \
        const uint32_t bb = sb + 2 * BG_ASTG + (s) * BG_ASTG;                   \
        _Pragma("unroll")                                                       \
        for (int i_ = 0; i_ < 4; i_++) {                                        \
            const int ch = tid + i_ * 256;                                      \
            const int row = ch >> 3, c16 = ch & 7;                              \
            cp16s(ab + row * BG_ROWB + c16 * 16,                                \
                  Abase + (size_t)row * lda + (t) * 64 + c16 * 8);              \
            cp16s(bb + row * BG_ROWB + c16 * 16,                                \
                  Bbase + (size_t)row * K + (t) * 64 + c16 * 8);                \
        }                                                                       \
    } while (0)

    BG_LOAD(0, 0); cp_commit();
    if (ntk > 1) { BG_LOAD(1, 1); }
    cp_commit();

    for (int t = 0; t < ntk; t++) {
        cp_wait1();
        __syncthreads();
        const int s = t & 1;
        const uint32_t aS = sb + s * BG_ASTG + (uint32_t)(wm * 64) * BG_ROWB + lmoff;
        const uint32_t bS = sb + 2 * BG_ASTG + s * BG_ASTG + (uint32_t)(wn * 32) * BG_ROWB + lmoff;

#pragma unroll
        for (int ks = 0; ks < 4; ks++) {
            const uint32_t kb = ks * 32;
            uint32_t af[4][4];
#pragma unroll
            for (int mi = 0; mi < 4; mi++)
                ldsm_x4(af[mi][0], af[mi][1], af[mi][2], af[mi][3],
                        aS + (uint32_t)(mi * 16) * BG_ROWB + kb);
            uint32_t b00, b01, b02, b03, b10, b11, b12, b13;
            ldsm_x4(b00, b01, b02, b03, bS + kb);
            ldsm_x4(b10, b11, b12, b13, bS + 16u * BG_ROWB + kb);
            uint32_t bf4[4][2] = {{b00, b02}, {b01, b03}, {b10, b12}, {b11, b13}};
#pragma unroll
            for (int mi = 0; mi < 4; mi++)
#pragma unroll
                for (int nj = 0; nj < 4; nj++)
                    mma_bf16(acc[mi][nj], af[mi], bf4[nj]);
        }
        __syncthreads();
        if (t + 2 < ntk) { BG_LOAD(s, t + 2); }
        cp_commit();
    }

    // ---------------- epilogue ----------------
    const bool do_relu = (flags & FLAG_RELU) != 0;
    const bool do_gate = (flags & FLAG_GATE) != 0;
    const bool wf32    = (flags & FLAG_WF32) != 0;
    const bool wbf16   = (flags & FLAG_WBF16) != 0;
    const bool wtf32   = (flags & FLAG_WTF32) != 0;
    const int  eblk    = n0 >> 11;

#pragma unroll
    for (int mi = 0; mi < 4; mi++) {
#pragma unroll
        for (int half = 0; half < 2; half++) {
            const int mrow = m0 + wm * 64 + mi * 16 + r + half * 8;
            const float rsv = do_gate ? gates[(size_t)mrow * E_ + eblk] : 1.f;
            const size_t rowbase = (size_t)mrow * ldc;
#pragma unroll
            for (int nj = 0; nj < 4; nj++) {
                const int ncol = n0 + wn * 32 + nj * 8 + 2 * c;
                float v0 = acc[mi][nj][half * 2 + 0];
                float v1 = acc[mi][nj][half * 2 + 1];
                if (bias) { v0 += bias[ncol]; v1 += bias[ncol + 1]; }
                if (do_relu) { v0 = fmaxf(v0, 0.f); v1 = fmaxf(v1, 0.f); }
                v0 *= rsv; v1 *= rsv;
                if (res) { v0 += res[rowbase + ncol]; v1 += res[rowbase + ncol + 1]; }
                if (wtf32) {
                    v0 = __uint_as_float(f2tf32(v0));
                    v1 = __uint_as_float(f2tf32(v1));
                }
                if (wf32)  *(float2*)&Cf[rowbase + ncol] = make_float2(v0, v1);
                if (wbf16) *(__nv_bfloat162*)&Cb[rowbase + ncol] = __floats2bfloat162_rn(v0, v1);
            }
        }
    }
#undef BG_LOAD
}

static inline void bgemm(const __nv_bfloat16* A, int lda, const __nv_bfloat16* W, int K,
                         const float* bias, const float* res, const float* gates,
                         float* Cf, __nv_bfloat16* Cb, int ldc, int M, int N, int flags)
{
    dim3 grid(N / 128, M / 128);
    bgemm_kernel<<<grid, 256, BG_SMEM_BYTES>>>(A, lda, W, K, bias, res, gates, Cf, Cb, ldc, N, flags);
}

// ---------------- flash attention: 128 queries/CTA, 256 threads (R14) -------
#define ATT_STG  8960
#define KS_STR 68
#define VS_STR 72
#define PQ_OFF 17920
#define QS_STR 68
#define PS_STR 76
#define PS_WARP 1216
#define ATTN_SMEM_BYTES 110592

template<bool CAUSAL>
__global__ void __launch_bounds__(256)
fattn_kernel(const float* __restrict__ Q, int q_ld,
             const float* __restrict__ Kp, const float* __restrict__ Vp, int kv_ld,
             __nv_bfloat16* __restrict__ Ob, int Sk)
{
    extern __shared__ float smf[];
    uint32_t* smu = (uint32_t*)smf;

    const int b = blockIdx.z, head = blockIdx.y;
    const int qt = CAUSAL ? (gridDim.x - 1 - blockIdx.x) : blockIdx.x;  // LPT
    const int tid  = threadIdx.x;
    const int w    = tid >> 5;
    const int lane = tid & 31;
    const int r = lane >> 2;
    const int c = lane & 3;
    const int wbase = w * 16;

    const float* Qg = Q + ((size_t)b * S_ + qt * 128) * q_ld + head * DH_;
#pragma unroll
    for (int i = 0; i < 8; i++) {
        const int idx = i * 256 + tid;
        const int row = idx >> 4;
        const int c4  = (idx & 15) * 4;
        *(float4*)&smf[PQ_OFF + row * QS_STR + c4] =
            *(const float4*)(Qg + (size_t)row * q_ld + c4);
    }
    __syncthreads();

    uint32_t aq[8][4];
#pragma unroll
    for (int kt = 0; kt < 8; kt++) {
        aq[kt][0] = f2tf32(0.125f * smf[PQ_OFF + (wbase + r)     * QS_STR + kt * 8 + c]);
        aq[kt][1] = f2tf32(0.125f * smf[PQ_OFF + (wbase + r + 8) * QS_STR + kt * 8 + c]);
        aq[kt][2] = f2tf32(0.125f * smf[PQ_OFF + (wbase + r)     * QS_STR + kt * 8 + c + 4]);
        aq[kt][3] = f2tf32(0.125f * smf[PQ_OFF + (wbase + r + 8) * QS_STR + kt * 8 + c + 4]);
    }

    float accO[8][4];
#pragma unroll
    for (int nj = 0; nj < 8; nj++)
#pragma unroll
        for (int q = 0; q < 4; q++) accO[nj][q] = 0.f;
    float mrow[2] = {-1e30f, -1e30f};
    float lrow[2] = {0.f, 0.f};

    const int ntiles = CAUSAL ? (2 * qt + 2) : (Sk >> 6);

#define ATT_LOAD(s, t) do {                                                      \
        const float* Kg_ = Kp + ((size_t)b * Sk + (t) * 64) * kv_ld + head * DH_;\
        const float* Vg_ = Vp + ((size_t)b * Sk + (t) * 64) * kv_ld + head * DH_;\
        float* ks_ = smf + (s) * ATT_STG;                                        \
        float* vs_ = smf + (s) * ATT_STG + 4352;                                 \
        _Pragma("unroll")                                                        \
        for (int i_ = 0; i_ < 4; i_++) {                                         \
            const int idx_ = i_ * 256 + tid;                                     \
            const int row_ = idx_ >> 4;                                          \
            const int c4_  = (idx_ & 15) * 4;                                    \
            cp16(ks_ + row_ * KS_STR + c4_, Kg_ + (size_t)row_ * kv_ld + c4_);   \
            cp16(vs_ + row_ * VS_STR + c4_, Vg_ + (size_t)row_ * kv_ld + c4_);   \
        }                                                                        \
    } while (0)

    ATT_LOAD(0, 0);
    cp_commit();

    for (int t = 0; t < ntiles; t++) {
        __syncthreads();
        if (t + 1 < ntiles) {
            ATT_LOAD((t + 1) & 1, t + 1);
            cp_commit();
            cp_wait1();
        } else {
            cp_wait0();
        }
        __syncthreads();

        const uint32_t ks0 = (uint32_t)((t & 1) * ATT_STG);
        const uint32_t vs0 = ks0 + 4352;

        float accS[8][4];
#pragma unroll
        for (int nj = 0; nj < 8; nj++)
#pragma unroll
            for (int q = 0; q < 4; q++) accS[nj][q] = 0.f;
#pragma unroll
        for (int kt = 0; kt < 8; kt++) {
#pragma unroll
            for (int nj = 0; nj < 8; nj++) {
                uint32_t bv[2];
                bv[0] = smu[ks0 + (nj * 8 + r) * KS_STR + kt * 8 + c];
                bv[1] = smu[ks0 + (nj * 8 + r) * KS_STR + kt * 8 + c + 4];
                mma_tf32(accS[nj], aq[kt], bv);
            }
        }

        if (CAUSAL && t >= 2 * qt) {
            const int koff = (t - 2 * qt) * 64;
#pragma unroll
            for (int nj = 0; nj < 8; nj++) {
                const int key0 = koff + nj * 8 + 2 * c;
#pragma unroll
                for (int q = 0; q < 4; q++) {
                    const int key  = key0 + (q & 1);
                    const int qrow = wbase + r + (q >> 1) * 8;
                    if (key > qrow) accS[nj][q] = -1e30f;
                }
            }
        }

#pragma unroll
        for (int hh = 0; hh < 2; hh++) {
            float vmax = -1e30f;
#pragma unroll
            for (int nj = 0; nj < 8; nj++)
                vmax = fmaxf(vmax, fmaxf(accS[nj][2 * hh], accS[nj][2 * hh + 1]));
            vmax = fmaxf(vmax, __shfl_xor_sync(0xffffffffu, vmax, 1));
            vmax = fmaxf(vmax, __shfl_xor_sync(0xffffffffu, vmax, 2));
            const float mnew = fmaxf(mrow[hh], vmax);
            const float corr = __expf(mrow[hh] - mnew);
            float psum = 0.f;
            uint32_t* Pw = smu + PQ_OFF + w * PS_WARP + (r + 8 * hh) * PS_STR + 2 * c;
#pragma unroll
            for (int nj = 0; nj < 8; nj++) {
                const float p0 = __expf(accS[nj][2 * hh]     - mnew);
                const float p1 = __expf(accS[nj][2 * hh + 1] - mnew);
                psum += p0 + p1;
                *(uint2*)&Pw[nj * 8] = make_uint2(f2tf32(p0), f2tf32(p1));
                accO[nj][2 * hh]     *= corr;
                accO[nj][2 * hh + 1] *= corr;
            }
            psum += __shfl_xor_sync(0xffffffffu, psum, 1);
            psum += __shfl_xor_sync(0xffffffffu, psum, 2);
            lrow[hh] = lrow[hh] * corr + psum;
            mrow[hh] = mnew;
        }
        __syncwarp();

        const uint32_t* Pb = smu + PQ_OFF + w * PS_WARP;
#pragma unroll
        for (int kt = 0; kt < 8; kt++) {
            uint32_t ap[4];
            ap[0] = Pb[r       * PS_STR + kt * 8 + c];
            ap[1] = Pb[(r + 8) * PS_STR + kt * 8 + c];
            ap[2] = Pb[r       * PS_STR + kt * 8 + c + 4];
            ap[3] = Pb[(r + 8) * PS_STR + kt * 8 + c + 4];
#pragma unroll
            for (int nj = 0; nj < 8; nj++) {
                uint32_t bv[2];
                bv[0] = smu[vs0 + (kt * 8 + c)     * VS_STR + nj * 8 + r];
                bv[1] = smu[vs0 + (kt * 8 + c + 4) * VS_STR + nj * 8 + r];
                mma_tf32(accO[nj], ap, bv);
            }
        }
    }
#undef ATT_LOAD

    const float inv0 = 1.f / lrow[0];
    const float inv1 = 1.f / lrow[1];
    const int row0 = qt * 128 + wbase + r;
    __nv_bfloat16* Obp = Ob + ((size_t)b * S_ + row0) * D_ + head * DH_;
#pragma unroll
    for (int nj = 0; nj < 8; nj++) {
        const int col = nj * 8 + 2 * c;
        *(__nv_bfloat162*)&Obp[col] = __floats2bfloat162_rn(accO[nj][0] * inv0, accO[nj][1] * inv0);
        *(__nv_bfloat162*)&Obp[(size_t)8 * D_ + col] =
            __floats2bfloat162_rn(accO[nj][2] * inv1, accO[nj][3] * inv1);
    }
}

// ---------------- LayerNorm kernels ----------------
__global__ void __launch_bounds__(256)
ln_kernel(const float* __restrict__ a,
          const float* __restrict__ g, const float* __restrict__ be,
          float* __restrict__ out, __nv_bfloat16* __restrict__ outb)
{
    const int row = blockIdx.x;
    const int t = threadIdx.x;
    const size_t base = (size_t)row * D_;
    float v0 = a[base + t];
    float v1 = a[base + t + 256];

    float s = v0 + v1, ss = v0 * v0 + v1 * v1;
    const int lane = t & 31, w = t >> 5;
    __shared__ float shs[8], shss[8];
#pragma unroll
    for (int off = 16; off; off >>= 1) {
        s  += __shfl_down_sync(0xffffffffu, s,  off);
        ss += __shfl_down_sync(0xffffffffu, ss, off);
    }
    if (lane == 0) { shs[w] = s; shss[w] = ss; }
    __syncthreads();
    __shared__ float mean_sh, inv_sh;
    if (t == 0) {
        float S = 0.f, SS = 0.f;
#pragma unroll
        for (int i = 0; i < 8; i++) { S += shs[i]; SS += shss[i]; }
        float mean = S * (1.f / (float)D_);
        float var  = SS * (1.f / (float)D_) - mean * mean;
        mean_sh = mean;
        inv_sh  = rsqrtf(var + EPS_);
    }
    __syncthreads();
    float mean = mean_sh, inv = inv_sh;
    float o0 = (v0 - mean) * inv * g[t]       + be[t];
    float o1 = (v1 - mean) * inv * g[t + 256] + be[t + 256];
    out[base + t]       = o0;
    out[base + t + 256] = o1;
    if (outb) {
        outb[base + t]       = __float2bfloat16_rn(o0);
        outb[base + t + 256] = __float2bfloat16_rn(o1);
    }
}

// LN2 + fused gate: out = LN(a)*g+be; gates = softmax(out @ gw + gb)
__global__ void __launch_bounds__(256)
ln2g_kernel(const float* __restrict__ a,
            const float* __restrict__ g, const float* __restrict__ be,
            const float* __restrict__ gw, const float* __restrict__ gb,
            float* __restrict__ out, __nv_bfloat16* __restrict__ outb)
{
    const int row = blockIdx.x;
    const int t = threadIdx.x;
    const size_t base = (size_t)row * D_;
    float v0 = a[base + t];
    float v1 = a[base + t + 256];

    float s = v0 + v1, ss = v0 * v0 + v1 * v1;
    const int lane = t & 31, w = t >> 5;
    __shared__ float shs[8], shss[8];
#pragma unroll
    for (int off = 16; off; off >>= 1) {
        s  += __shfl_down_sync(0xffffffffu, s,  off);
        ss += __shfl_down_sync(0xffffffffu, ss, off);
    }
    if (lane == 0) { shs[w] = s; shss[w] = ss; }
    __syncthreads();
    __shared__ float mean_sh, inv_sh;
    if (t == 0) {
        float S = 0.f, SS = 0.f;
#pragma unroll
        for (int i = 0; i < 8; i++) { S += shs[i]; SS += shss[i]; }
        float mean = S * (1.f / (float)D_);
        float var  = SS * (1.f / (float)D_) - mean * mean;
        mean_sh = mean;
        inv_sh  = rsqrtf(var + EPS_);
    }
    __syncthreads();
    float mean = mean_sh, inv = inv_sh;
    float o0 = (v0 - mean) * inv * g[t]       + be[t];
    float o1 = (v1 - mean) * inv * g[t + 256] + be[t + 256];
    out[base + t]       = o0;
    out[base + t + 256] = o1;
    outb[base + t]       = __float2bfloat16_rn(o0);
    outb[base + t + 256] = __float2bfloat16_rn(o1);

    // ---- fused gate logits: a_e = sum_d out[d]*gw[d][e] ----
    const float4 w0 = *(const float4*)&gw[t * 4];
    const float4 w1 = *(const float4*)&gw[(t + 256) * 4];
    float a0 = o0 * w0.x + o1 * w1.x;
    float a1 = o0 * w0.y + o1 * w1.y;
    float a2 = o0 * w0.z + o1 * w1.z;
    float a3 = o0 * w0.w + o1 * w1.w;
#pragma unroll
    for (int off = 16; off; off >>= 1) {
        a0 += __shfl_down_sync(0xffffffffu, a0, off);
        a1 += __shfl_down_sync(0xffffffffu, a1, off);
        a2 += __shfl_down_sync(0xffffffffu, a2, off);
        a3 += __shfl_down_sync(0xffffffffu, a3, off);
    }
    __shared__ float shg[8][4];
    if (lane == 0) { shg[w][0] = a0; shg[w][1] = a1; shg[w][2] = a2; shg[w][3] = a3; }
    __syncthreads();
    if (t == 0) {
        float l0 = gb[0], l1 = gb[1], l2 = gb[2], l3 = gb[3];
#pragma unroll
        for (int i = 0; i < 8; i++) {
            l0 += shg[i][0]; l1 += shg[i][1]; l2 += shg[i][2]; l3 += shg[i][3];
        }
        float mx = fmaxf(fmaxf(l0, l1), fmaxf(l2, l3));
        float e0 = __expf(l0 - mx), e1 = __expf(l1 - mx);
        float e2 = __expf(l2 - mx), e3 = __expf(l3 - mx);
        float si = 1.f / (e0 + e1 + e2 + e3);
        float p0 = e0 * si, p1 = e1 * si, p2 = e2 * si, p3 = e3 * si;
        float* gp = g_gates + (size_t)row * E_;
        gp[0] = p0; gp[1] = p1; gp[2] = p2; gp[3] = p3;
        atomicAdd(&g_gsum[0], p0);
        atomicAdd(&g_gsum[1], p1);
        atomicAdd(&g_gsum[2], p2);
        atomicAdd(&g_gsum[3], p3);
    }
}

__global__ void __launch_bounds__(256)
ln3_kernel(const float* __restrict__ xb, const float* __restrict__ y,
           const float* __restrict__ gates, const float* __restrict__ b2,
           const float* __restrict__ g, const float* __restrict__ be,
           float* __restrict__ out)
{
    const int row = blockIdx.x;
    const int t = threadIdx.x;
    const size_t base = (size_t)row * D_;
    const float ga0 = gates[(size_t)row * E_ + 0];
    const float ga1 = gates[(size_t)row * E_ + 1];
    const float ga2 = gates[(size_t)row * E_ + 2];
    const float ga3 = gates[(size_t)row * E_ + 3];
    float gb0 = ga0 * b2[t]        + ga1 * b2[D_ + t]        + ga2 * b2[2*D_ + t]        + ga3 * b2[3*D_ + t];
    float gb1 = ga0 * b2[t + 256]  + ga1 * b2[D_ + t + 256]  + ga2 * b2[2*D_ + t + 256]  + ga3 * b2[3*D_ + t + 256];
    float v0 = xb[base + t]       + y[base + t]       + gb0;
    float v1 = xb[base + t + 256] + y[base + t + 256] + gb1;

    float s = v0 + v1, ss = v0 * v0 + v1 * v1;
    const int lane = t & 31, w = t >> 5;
    __shared__ float shs[8], shss[8];
#pragma unroll
    for (int off = 16; off; off >>= 1) {
        s  += __shfl_down_sync(0xffffffffu, s,  off);
        ss += __shfl_down_sync(0xffffffffu, ss, off);
    }
    if (lane == 0) { shs[w] = s; shss[w] = ss; }
    __syncthreads();
    __shared__ float mean_sh, inv_sh;
    if (t == 0) {
        float S = 0.f, SS = 0.f;
#pragma unroll
        for (int i = 0; i < 8; i++) { S += shs[i]; SS += shss[i]; }
        float mean = S * (1.f / (float)D_);
        float var  = SS * (1.f / (float)D_) - mean * mean;
        mean_sh = mean;
        inv_sh  = rsqrtf(var + EPS_);
    }
    __syncthreads();
    float mean = mean_sh, inv = inv_sh;
    out[base + t]       = (v0 - mean) * inv * g[t]       + be[t];
    out[base + t + 256] = (v1 - mean) * inv * g[t + 256] + be[t + 256];
}

// ---------------- host orchestration ----------------
extern "C" void kernel_launch(void* const* d_in, const int* in_sizes, int n_in,
                              void* d_out, int out_size)
{
    const float* x      = (const float*)d_in[0];
    const float* cross  = (const float*)d_in[1];
    const float* sa_wq  = (const float*)d_in[2];
    const float* sa_bq  = (const float*)d_in[3];
    const float* sa_wk  = (const float*)d_in[4];
    const float* sa_bk  = (const float*)d_in[5];
    const float* sa_wv  = (const float*)d_in[6];
    const float* sa_bv  = (const float*)d_in[7];
    const float* sa_wo  = (const float*)d_in[8];
    const float* sa_bo  = (const float*)d_in[9];
    const float* ca_wq  = (const float*)d_in[10];
    const float* ca_bq  = (const float*)d_in[11];
    const float* ca_wk  = (const float*)d_in[12];
    const float* ca_bk  = (const float*)d_in[13];
    const float* ca_wv  = (const float*)d_in[14];
    const float* ca_bv  = (const float*)d_in[15];
    const float* ca_wo  = (const float*)d_in[16];
    const float* ca_bo  = (const float*)d_in[17];
    const float* gate_w = (const float*)d_in[18];
    const float* gate_b = (const float*)d_in[19];
    const float* exp_w1 = (const float*)d_in[20];
    const float* exp_b1 = (const float*)d_in[21];
    const float* exp_w2 = (const float*)d_in[22];
    const float* exp_b2 = (const float*)d_in[23];
    const float* n1_g   = (const float*)d_in[24];
    const float* n1_b   = (const float*)d_in[25];
    const float* n2_g   = (const float*)d_in[26];
    const float* n2_b   = (const float*)d_in[27];
    const float* n3_g   = (const float*)d_in[28];
    const float* n3_b   = (const float*)d_in[29];
    float* out = (float*)d_out;

    float *qkv, *pre, *xa, *xb, *y, *gates, *bqkv, *bcakv;
    __nv_bfloat16 *attbf, *xabf, *xbbf, *hbf, *xbf, *crbf;
    __nv_bfloat16 *wqkvt, *wsaot, *wcaqt, *wcakvt, *wcaot, *w1t, *w2t;
    cudaGetSymbolAddress((void**)&qkv,    g_qkv);
    cudaGetSymbolAddress((void**)&pre,    g_pre);
    cudaGetSymbolAddress((void**)&xa,     g_xa);
    cudaGetSymbolAddress((void**)&xb,     g_xb);
    cudaGetSymbolAddress((void**)&y,      g_y);
    cudaGetSymbolAddress((void**)&gates,  g_gates);
    cudaGetSymbolAddress((void**)&bqkv,   g_bqkv);
    cudaGetSymbolAddress((void**)&bcakv,  g_bcakv);
    cudaGetSymbolAddress((void**)&attbf,  g_attbf);
    cudaGetSymbolAddress((void**)&xabf,   g_xabf);
    cudaGetSymbolAddress((void**)&xbbf,   g_xbbf);
    cudaGetSymbolAddress((void**)&hbf,    g_hbf);
    cudaGetSymbolAddress((void**)&xbf,    g_xbf);
    cudaGetSymbolAddress((void**)&crbf,   g_crbf);
    cudaGetSymbolAddress((void**)&wqkvt,  g_wqkvt);
    cudaGetSymbolAddress((void**)&wsaot,  g_wsaot);
    cudaGetSymbolAddress((void**)&wcaqt,  g_wcaqt);
    cudaGetSymbolAddress((void**)&wcakvt, g_wcakvt);
    cudaGetSymbolAddress((void**)&wcaot,  g_wcaot);
    cudaGetSymbolAddress((void**)&w1t,    g_w1t);
    cudaGetSymbolAddress((void**)&w2t,    g_w2t);

    static bool attr_done = false;
    if (!attr_done) {
        cudaFuncSetAttribute(fattn_kernel<true>,
                             cudaFuncAttributeMaxDynamicSharedMemorySize, ATTN_SMEM_BYTES);
        cudaFuncSetAttribute(fattn_kernel<false>,
                             cudaFuncAttributeMaxDynamicSharedMemorySize, ATTN_SMEM_BYTES);
        cudaFuncSetAttribute(bgemm_kernel,
                             cudaFuncAttributeMaxDynamicSharedMemorySize, BG_SMEM_BYTES);
        attr_done = true;
    }

    dim3 tb(32, 8);

    // ---- prep ----
    zero_gsum_kernel<<<1, 32>>>();
    cvtbf_kernel<<<(BSROWS*D_/4 + 255)/256, 256>>>(x, xbf, BSROWS*D_/4);
    cvtbf_kernel<<<(BTROWS*D_/4 + 255)/256, 256>>>(cross, crbf, BTROWS*D_/4);
    tpackz_kernel<<<dim3(16,16,3), tb>>>(sa_wq, sa_wk, sa_wv, wqkvt);
    pack3f_kernel<<<2, 256>>>(sa_bq, sa_bk, sa_bv, bqkv);
    bgemm(xbf, 512, wqkvt, 512, bqkv, nullptr, nullptr, qkv, nullptr, 1536,
          BSROWS, 1536, FLAG_WF32 | FLAG_WTF32);

    tpack3_kernel<<<dim3(16,16,1), tb>>>(sa_wo, 512, 0, wsaot, 512, 0, 0, 0, 0);
    tpack3_kernel<<<dim3(16,16,1), tb>>>(ca_wq, 512, 0, wcaqt, 512, 0, 0, 0, 0);
    tpackz_kernel<<<dim3(16,16,2), tb>>>(ca_wk, ca_wv, nullptr, wcakvt);
    tpack3_kernel<<<dim3(16,16,1), tb>>>(ca_wo, 512, 0, wcaot, 512, 0, 0, 0, 0);
    tpack3_kernel<<<dim3(64,16,4), tb>>>(exp_w1, DF_, (size_t)D_*DF_, w1t, 512, 0, 0, DF_, 0);
    tpack3_kernel<<<dim3(16,64,4), tb>>>(exp_w2, 512, (size_t)DF_*D_, w2t, 8192, 0, 0, 0, DF_);
    pack3f_kernel<<<2, 256>>>(ca_bk, ca_bv, nullptr, bcakv);

    // ---- self-attention block ----
    fattn_kernel<true><<<dim3(S_/128, H_, B_), 256, ATTN_SMEM_BYTES>>>(
        qkv, 1536, qkv + 512, qkv + 1024, 1536, attbf, S_);
    bgemm(attbf, 512, wsaot, 512, sa_bo, /*res=*/x, nullptr, pre, nullptr, 512,
          BSROWS, 512, FLAG_WF32);
    ln_kernel<<<BSROWS, 256>>>(pre, n1_g, n1_b, xa, xabf);

    // ---- cross-attention block ----
    float* qc  = qkv;
    float* kvc = qkv + (size_t)BSROWS * 512;
    bgemm(xabf, 512, wcaqt, 512, ca_bq, nullptr, nullptr, qc, nullptr, 512,
          BSROWS, 512, FLAG_WF32 | FLAG_WTF32);
    bgemm(crbf, 512, wcakvt, 512, bcakv, nullptr, nullptr, kvc, nullptr, 1024,
          BTROWS, 1024, FLAG_WF32 | FLAG_WTF32);
    fattn_kernel<false><<<dim3(S_/128, H_, B_), 256, ATTN_SMEM_BYTES>>>(
        qc, 512, kvc, kvc + 512, 1024, attbf, T_);
    bgemm(attbf, 512, wcaot, 512, ca_bo, /*res=*/xa, nullptr, pre, nullptr, 512,
          BSROWS, 512, FLAG_WF32);
    // LN2 with fused gate (replaces ln_kernel + gate_kernel)
    ln2g_kernel<<<BSROWS, 256>>>(pre, n2_g, n2_b, gate_w, gate_b, xb, xbbf);

    // ---- MoE (monolithic) ----
    aux_kernel<<<1, 1>>>(out, out_size);
    bgemm(xbbf, 512, w1t, 512, exp_b1, nullptr, gates, nullptr, hbf, 8192,
          BSROWS, 8192, FLAG_RELU | FLAG_GATE | FLAG_WBF16);
    bgemm(hbf, 8192, w2t, 8192, nullptr, nullptr, nullptr, y, nullptr, 512,
          BSROWS, 512, FLAG_WF32);
    ln3_kernel<<<BSROWS, 256>>>(xb, y, gates, exp_b2, n3_g, n3_b, out);
}